// round 1
// baseline (speedup 1.0000x reference)
#include <cuda_runtime.h>
#include <cstdint>

// ---------------- problem dimensions (fixed by the dataset) ----------------
#define M_DIM 16384   // 4 * 4096 tokens
#define D_DIM 1024
#define H_DIM 4096

// ---------------- device scratch (static, allocation-free) ----------------
__device__ int8_t  g_xq[(size_t)M_DIM * D_DIM];     // 16 MB
__device__ int8_t  g_hq[(size_t)M_DIM * H_DIM];     // 64 MB
__device__ float   g_h [(size_t)M_DIM * H_DIM];     // 256 MB
__device__ int8_t  g_w1q[(size_t)H_DIM * D_DIM];    // 4 MB
__device__ int8_t  g_w2q[(size_t)D_DIM * H_DIM];    // 4 MB
__device__ int     g_rs1[H_DIM];
__device__ int     g_rs2[D_DIM];
// stats: 0=min_x(enc) 1=max_x(enc) 2=absmax_w1 3=absmax_w2 4=min_h(enc) 5=max_h(enc)
__device__ unsigned g_stats[6];
// scales: 0=sx 1=sw1 2=sw2 3=s1(sx*sw1) 4=sh 5=s2(sh*sw2)
__device__ float    g_scale[6];
__device__ int      g_zp[2];   // 0=zx 1=zh

// ---------------- helpers ----------------
__device__ __forceinline__ unsigned fenc(float f) {
    unsigned u = __float_as_uint(f);
    return (u & 0x80000000u) ? ~u : (u | 0x80000000u);
}
__device__ __forceinline__ float fdec(unsigned e) {
    return __uint_as_float((e & 0x80000000u) ? (e ^ 0x80000000u) : ~e);
}
__device__ __forceinline__ float gelu_exact(float v) {
    return 0.5f * v * (1.0f + erff(v * 0.7071067811865476f));
}

#define CP_ASYNC16(dst_u32, src_ptr) \
    asm volatile("cp.async.cg.shared.global [%0], [%1], 16;\n" :: "r"(dst_u32), "l"(src_ptr))
#define CP_COMMIT() asm volatile("cp.async.commit_group;\n" ::: "memory")
#define CP_WAIT1()  asm volatile("cp.async.wait_group 1;\n" ::: "memory")
#define CP_WAIT0()  asm volatile("cp.async.wait_group 0;\n" ::: "memory")

__device__ __forceinline__ void mma_s8(int* c, const uint32_t* a, const uint32_t* b) {
    asm volatile(
        "mma.sync.aligned.m16n8k32.row.col.s32.s8.s8.s32 "
        "{%0,%1,%2,%3}, {%4,%5,%6,%7}, {%8,%9}, {%0,%1,%2,%3};\n"
        : "+r"(c[0]), "+r"(c[1]), "+r"(c[2]), "+r"(c[3])
        : "r"(a[0]), "r"(a[1]), "r"(a[2]), "r"(a[3]), "r"(b[0]), "r"(b[1]));
}

// ---------------- init ----------------
__global__ void k_init() {
    if (threadIdx.x == 0) {
        g_stats[0] = 0xFFFFFFFFu; g_stats[1] = 0u;
        g_stats[2] = 0u;          g_stats[3] = 0u;
        g_stats[4] = 0xFFFFFFFFu; g_stats[5] = 0u;
    }
}

// ---------------- global min/max of x ----------------
__global__ void k_minmax_x(const float4* __restrict__ x, int n4) {
    float lmin = 3.4e38f, lmax = -3.4e38f;
    for (int i = blockIdx.x * blockDim.x + threadIdx.x; i < n4; i += gridDim.x * blockDim.x) {
        float4 v = x[i];
        lmin = fminf(lmin, fminf(fminf(v.x, v.y), fminf(v.z, v.w)));
        lmax = fmaxf(lmax, fmaxf(fmaxf(v.x, v.y), fmaxf(v.z, v.w)));
    }
    #pragma unroll
    for (int o = 16; o; o >>= 1) {
        lmin = fminf(lmin, __shfl_xor_sync(0xffffffffu, lmin, o));
        lmax = fmaxf(lmax, __shfl_xor_sync(0xffffffffu, lmax, o));
    }
    __shared__ float sm[2][8];
    if ((threadIdx.x & 31) == 0) { sm[0][threadIdx.x >> 5] = lmin; sm[1][threadIdx.x >> 5] = lmax; }
    __syncthreads();
    if (threadIdx.x == 0) {
        float m = sm[0][0], M = sm[1][0];
        #pragma unroll
        for (int w = 1; w < 8; w++) { m = fminf(m, sm[0][w]); M = fmaxf(M, sm[1][w]); }
        atomicMin(&g_stats[0], fenc(m));
        atomicMax(&g_stats[1], fenc(M));
    }
}

// ---------------- abs-max of a weight tensor ----------------
__global__ void k_absmax(const float4* __restrict__ w, int n4, int slot) {
    float lmax = 0.0f;
    for (int i = blockIdx.x * blockDim.x + threadIdx.x; i < n4; i += gridDim.x * blockDim.x) {
        float4 v = w[i];
        lmax = fmaxf(lmax, fmaxf(fmaxf(fabsf(v.x), fabsf(v.y)), fmaxf(fabsf(v.z), fabsf(v.w))));
    }
    #pragma unroll
    for (int o = 16; o; o >>= 1) lmax = fmaxf(lmax, __shfl_xor_sync(0xffffffffu, lmax, o));
    __shared__ float sm[8];
    if ((threadIdx.x & 31) == 0) sm[threadIdx.x >> 5] = lmax;
    __syncthreads();
    if (threadIdx.x == 0) {
        float M = sm[0];
        #pragma unroll
        for (int w2 = 1; w2 < 8; w2++) M = fmaxf(M, sm[w2]);
        atomicMax(&g_stats[slot], __float_as_uint(M));  // nonneg floats: bits are monotone
    }
}

// ---------------- finalize input/weight scales ----------------
__global__ void k_fin1() {
    if (threadIdx.x != 0) return;
    float an = fdec(g_stats[0]), ax = fdec(g_stats[1]);
    float sx = fmaxf(__fdiv_rn(ax - an, 255.0f), 1e-8f);
    float zxf = rintf(__fdiv_rn(-an, sx)) - 128.0f;
    zxf = fminf(fmaxf(zxf, -128.0f), 127.0f);
    float sw1 = fmaxf(__fdiv_rn(__uint_as_float(g_stats[2]), 127.0f), 1e-8f);
    float sw2 = fmaxf(__fdiv_rn(__uint_as_float(g_stats[3]), 127.0f), 1e-8f);
    g_scale[0] = sx; g_scale[1] = sw1; g_scale[2] = sw2;
    g_scale[3] = sx * sw1;
    g_zp[0] = (int)zxf;
}

// ---------------- finalize h scales (after GEMM1) ----------------
__global__ void k_fin2() {
    if (threadIdx.x != 0) return;
    float hn = fdec(g_stats[4]), hx = fdec(g_stats[5]);
    float sh = fmaxf(__fdiv_rn(hx - hn, 255.0f), 1e-8f);
    float zhf = rintf(__fdiv_rn(-hn, sh)) - 128.0f;
    zhf = fminf(fmaxf(zhf, -128.0f), 127.0f);
    g_scale[4] = sh;
    g_scale[5] = sh * g_scale[2];
    g_zp[1] = (int)zhf;
}

// ---------------- activation quantize (x or h) ----------------
// which==0: src=x arg -> g_xq ; which==1: src=g_h -> g_hq
__global__ void k_quant(const float4* __restrict__ xsrc, size_t n4, int which) {
    const float4* src = which ? (const float4*)g_h : xsrc;
    char4* dst = which ? (char4*)g_hq : (char4*)g_xq;
    float s = which ? g_scale[4] : g_scale[0];
    float zp = (float)(which ? g_zp[1] : g_zp[0]);
    for (size_t i = blockIdx.x * (size_t)blockDim.x + threadIdx.x; i < n4;
         i += (size_t)gridDim.x * blockDim.x) {
        float4 v = src[i];
        float q0 = fminf(fmaxf(rintf(__fdiv_rn(v.x, s)) + zp, -128.0f), 127.0f);
        float q1 = fminf(fmaxf(rintf(__fdiv_rn(v.y, s)) + zp, -128.0f), 127.0f);
        float q2 = fminf(fmaxf(rintf(__fdiv_rn(v.z, s)) + zp, -128.0f), 127.0f);
        float q3 = fminf(fmaxf(rintf(__fdiv_rn(v.w, s)) + zp, -128.0f), 127.0f);
        char4 c; c.x = (char)(int)q0; c.y = (char)(int)q1; c.z = (char)(int)q2; c.w = (char)(int)q3;
        dst[i] = c;
    }
}

// ---------------- weight quantize + per-row sums ----------------
// which==0: W1 -> g_w1q/g_rs1 (cols=1024) ; which==1: W2 -> g_w2q/g_rs2 (cols=4096)
__global__ void k_quantw(const float* __restrict__ W, int cols, int which) {
    int8_t* wq = which ? g_w2q : g_w1q;
    int* rs = which ? g_rs2 : g_rs1;
    float sw = which ? g_scale[2] : g_scale[1];
    int row = blockIdx.x;
    const float4* src = (const float4*)(W + (size_t)row * cols);
    char4* dst = (char4*)(wq + (size_t)row * cols);
    int acc = 0;
    for (int c = threadIdx.x; c < (cols >> 2); c += blockDim.x) {
        float4 v = src[c];
        float q0 = fminf(fmaxf(rintf(__fdiv_rn(v.x, sw)), -127.0f), 127.0f);
        float q1 = fminf(fmaxf(rintf(__fdiv_rn(v.y, sw)), -127.0f), 127.0f);
        float q2 = fminf(fmaxf(rintf(__fdiv_rn(v.z, sw)), -127.0f), 127.0f);
        float q3 = fminf(fmaxf(rintf(__fdiv_rn(v.w, sw)), -127.0f), 127.0f);
        int i0 = (int)q0, i1 = (int)q1, i2 = (int)q2, i3 = (int)q3;
        acc += i0 + i1 + i2 + i3;
        char4 cc; cc.x = (char)i0; cc.y = (char)i1; cc.z = (char)i2; cc.w = (char)i3;
        dst[c] = cc;
    }
    #pragma unroll
    for (int o = 16; o; o >>= 1) acc += __shfl_xor_sync(0xffffffffu, acc, o);
    __shared__ int sm[8];
    if ((threadIdx.x & 31) == 0) sm[threadIdx.x >> 5] = acc;
    __syncthreads();
    if (threadIdx.x == 0) {
        int t = 0;
        #pragma unroll
        for (int w = 0; w < 8; w++) t += sm[w];
        rs[row] = t;
    }
}

// ---------------- int8 GEMM: C[M,N] = A[M,K] . B[N,K]^T, epilogue dequant ----------------
// MODE 1: GEMM1 -> gelu -> g_h (fp32) + global min/max of gelu output
// MODE 0: GEMM2 -> d_out (fp32)
#define BM 128
#define BN 128
#define BKT 64
#define SSTR 80   // padded smem row stride (bytes); 80 = 5*16 keeps 16B align, kills conflicts

template <int MODE>
__global__ __launch_bounds__(256, 2)
void k_gemm(const float* __restrict__ bias, int M, int N, int K, float* __restrict__ outp) {
    const int8_t* __restrict__ A = MODE ? g_xq : g_hq;
    const int8_t* __restrict__ B = MODE ? g_w1q : g_w2q;
    const int* __restrict__ rs   = MODE ? g_rs1 : g_rs2;
    float* __restrict__ out      = MODE ? g_h : outp;
    const float s = MODE ? g_scale[3] : g_scale[5];
    const int   z = MODE ? g_zp[0] : g_zp[1];

    __shared__ int8_t As[2][BM * SSTR];
    __shared__ int8_t Bs[2][BN * SSTR];

    const int tid = threadIdx.x;
    const int lane = tid & 31;
    const int wid = tid >> 5;
    const int warp_m = wid & 1;      // 2 warps over M
    const int warp_n = wid >> 1;     // 4 warps over N
    const int bm = blockIdx.y, bn = blockIdx.x;

    int c[4][4][4];
    #pragma unroll
    for (int i = 0; i < 4; i++)
        #pragma unroll
        for (int j = 0; j < 4; j++)
            #pragma unroll
            for (int k = 0; k < 4; k++) c[i][j][k] = 0;

    // tile loader: 128 rows x 64 bytes per matrix, 256 threads x 2 chunks x 16B
    auto load_tiles = [&](int k0, int stage) {
        #pragma unroll
        for (int i = 0; i < 2; i++) {
            int linear = tid + i * 256;
            int row = linear >> 2, seg = (linear & 3) * 16;
            const int8_t* srcA = A + (size_t)(bm * BM + row) * K + k0 + seg;
            unsigned dA = (unsigned)__cvta_generic_to_shared(&As[stage][row * SSTR + seg]);
            CP_ASYNC16(dA, srcA);
            const int8_t* srcB = B + (size_t)(bn * BN + row) * K + k0 + seg;
            unsigned dB = (unsigned)__cvta_generic_to_shared(&Bs[stage][row * SSTR + seg]);
            CP_ASYNC16(dB, srcB);
        }
    };

    const int KT = K / BKT;
    load_tiles(0, 0);
    CP_COMMIT();

    for (int kt = 0; kt < KT; kt++) {
        int stage = kt & 1;
        if (kt + 1 < KT) { load_tiles((kt + 1) * BKT, stage ^ 1); CP_COMMIT(); CP_WAIT1(); }
        else             { CP_WAIT0(); }
        __syncthreads();

        const int8_t* Ab = As[stage];
        const int8_t* Bb = Bs[stage];
        #pragma unroll
        for (int kk = 0; kk < BKT; kk += 32) {
            uint32_t a[4][4], b[4][2];
            #pragma unroll
            for (int im = 0; im < 4; im++) {
                int r = warp_m * 64 + im * 16 + (lane >> 2);
                const int8_t* p = Ab + r * SSTR + kk + (lane & 3) * 4;
                a[im][0] = *(const uint32_t*)p;
                a[im][1] = *(const uint32_t*)(p + 8 * SSTR);
                a[im][2] = *(const uint32_t*)(p + 16);
                a[im][3] = *(const uint32_t*)(p + 8 * SSTR + 16);
            }
            #pragma unroll
            for (int in = 0; in < 4; in++) {
                int r = warp_n * 32 + in * 8 + (lane >> 2);
                const int8_t* p = Bb + r * SSTR + kk + (lane & 3) * 4;
                b[in][0] = *(const uint32_t*)p;
                b[in][1] = *(const uint32_t*)(p + 16);
            }
            #pragma unroll
            for (int im = 0; im < 4; im++)
                #pragma unroll
                for (int in = 0; in < 4; in++)
                    mma_s8(c[im][in], a[im], b[in]);
        }
        __syncthreads();
    }

    // -------- epilogue --------
    float lmin = 3.4e38f, lmax = -3.4e38f;
    #pragma unroll
    for (int in = 0; in < 4; in++) {
        int col = bn * BN + warp_n * 32 + in * 8 + (lane & 3) * 2;
        int rs0 = rs[col], rs1v = rs[col + 1];
        float b0 = bias[col], b1v = bias[col + 1];
        #pragma unroll
        for (int im = 0; im < 4; im++) {
            int row = bm * BM + warp_m * 64 + im * 16 + (lane >> 2);
            float v0 = (float)(c[im][in][0] - z * rs0) * s + b0;
            float v1 = (float)(c[im][in][1] - z * rs1v) * s + b1v;
            float v2 = (float)(c[im][in][2] - z * rs0) * s + b0;
            float v3 = (float)(c[im][in][3] - z * rs1v) * s + b1v;
            if (MODE) {
                v0 = gelu_exact(v0); v1 = gelu_exact(v1);
                v2 = gelu_exact(v2); v3 = gelu_exact(v3);
                lmin = fminf(lmin, fminf(fminf(v0, v1), fminf(v2, v3)));
                lmax = fmaxf(lmax, fmaxf(fmaxf(v0, v1), fmaxf(v2, v3)));
            }
            float2* p0 = (float2*)(out + (size_t)row * N + col);
            float2* p1 = (float2*)(out + (size_t)(row + 8) * N + col);
            *p0 = make_float2(v0, v1);
            *p1 = make_float2(v2, v3);
        }
    }

    if (MODE) {
        #pragma unroll
        for (int o = 16; o; o >>= 1) {
            lmin = fminf(lmin, __shfl_xor_sync(0xffffffffu, lmin, o));
            lmax = fmaxf(lmax, __shfl_xor_sync(0xffffffffu, lmax, o));
        }
        __shared__ float red[2][8];
        if (lane == 0) { red[0][wid] = lmin; red[1][wid] = lmax; }
        __syncthreads();
        if (tid == 0) {
            float m = red[0][0], Mx = red[1][0];
            #pragma unroll
            for (int w = 1; w < 8; w++) { m = fminf(m, red[0][w]); Mx = fmaxf(Mx, red[1][w]); }
            atomicMin(&g_stats[4], fenc(m));
            atomicMax(&g_stats[5], fenc(Mx));
        }
    }
}

// ---------------- launch ----------------
extern "C" void kernel_launch(void* const* d_in, const int* in_sizes, int n_in,
                              void* d_out, int out_size) {
    const float* x  = (const float*)d_in[0];
    const float* W1 = (const float*)d_in[1];
    const float* b1 = (const float*)d_in[2];
    const float* W2 = (const float*)d_in[3];
    const float* b2 = (const float*)d_in[4];
    float* out = (float*)d_out;

    const size_t nx = (size_t)M_DIM * D_DIM;          // 16.7M
    const size_t nh = (size_t)M_DIM * H_DIM;          // 67.1M

    k_init<<<1, 32>>>();
    k_minmax_x<<<2048, 256>>>((const float4*)x, (int)(nx / 4));
    k_absmax<<<512, 256>>>((const float4*)W1, (int)((size_t)H_DIM * D_DIM / 4), 2);
    k_absmax<<<512, 256>>>((const float4*)W2, (int)((size_t)D_DIM * H_DIM / 4), 3);
    k_fin1<<<1, 32>>>();
    k_quant<<<2048, 256>>>((const float4*)x, nx / 4, 0);
    k_quantw<<<H_DIM, 256>>>(W1, D_DIM, 0);
    k_quantw<<<D_DIM, 256>>>(W2, H_DIM, 1);

    dim3 g1(H_DIM / BN, M_DIM / BM);   // (32, 128)
    k_gemm<1><<<g1, 256>>>(b1, M_DIM, H_DIM, D_DIM, nullptr);

    k_fin2<<<1, 32>>>();
    k_quant<<<4096, 256>>>(nullptr, nh / 4, 1);

    dim3 g2(D_DIM / BN, M_DIM / BM);   // (8, 128)
    k_gemm<0><<<g2, 256>>>(b2, M_DIM, D_DIM, H_DIM, out);
}

// round 4
// speedup vs baseline: 1.0226x; 1.0226x over previous
#include <cuda_runtime.h>
#include <cstdint>

// ---------------- problem dimensions (fixed by the dataset) ----------------
#define M_DIM 16384   // 4 * 4096 tokens
#define D_DIM 1024
#define H_DIM 4096

// NOTE (env constraint, Round 2 finding): harness PTX target is sm_103 (no 'a'),
// so tcgen05/TMEM are unavailable. Legacy mma.sync (IMMA) is the tensor path.
// Round 3 crash root cause: GEMM2 call passed (M_DIM, D_DIM) as (N, K). Fixed here.

// ---------------- device scratch (static, allocation-free) ----------------
__device__ __align__(128) int8_t  g_xq[(size_t)M_DIM * D_DIM];     // 16 MB
__device__ __align__(128) int8_t  g_hq[(size_t)M_DIM * H_DIM];     // 64 MB
__device__ __align__(128) float   g_h [(size_t)M_DIM * H_DIM];     // 256 MB
__device__ __align__(128) int8_t  g_w1q[(size_t)H_DIM * D_DIM];    // 4 MB
__device__ __align__(128) int8_t  g_w2q[(size_t)D_DIM * H_DIM];    // 4 MB
__device__ int     g_rs1[H_DIM];
__device__ int     g_rs2[D_DIM];
// stats: 0=min_x(enc) 1=max_x(enc) 2=absmax_w1 3=absmax_w2 4=min_h(enc) 5=max_h(enc)
__device__ unsigned g_stats[6];
// scales: 0=sx 1=sw1 2=sw2 3=s1(sx*sw1) 4=sh 5=s2(sh*sw2)
__device__ float    g_scale[6];
__device__ int      g_zp[2];   // 0=zx 1=zh

// ---------------- helpers ----------------
__device__ __forceinline__ unsigned fenc(float f) {
    unsigned u = __float_as_uint(f);
    return (u & 0x80000000u) ? ~u : (u | 0x80000000u);
}
__device__ __forceinline__ float fdec(unsigned e) {
    return __uint_as_float((e & 0x80000000u) ? (e ^ 0x80000000u) : ~e);
}
__device__ __forceinline__ float gelu_exact(float v) {
    return 0.5f * v * (1.0f + erff(v * 0.7071067811865476f));
}
__device__ __forceinline__ uint32_t smem_u32(const void* p) {
    uint32_t a;
    asm("{ .reg .u64 t; cvta.to.shared.u64 t, %1; cvt.u32.u64 %0, t; }" : "=r"(a) : "l"(p));
    return a;
}

#define CP_ASYNC16(dst_u32, src_ptr) \
    asm volatile("cp.async.cg.shared.global [%0], [%1], 16;\n" :: "r"(dst_u32), "l"(src_ptr))
#define CP_COMMIT() asm volatile("cp.async.commit_group;\n" ::: "memory")
#define CP_WAIT1()  asm volatile("cp.async.wait_group 1;\n" ::: "memory")

#define SWZ(off) ((off) ^ (((off) >> 3) & 0x70))

#define LDSM_X4(r0, r1, r2, r3, addr) \
    asm volatile("ldmatrix.sync.aligned.m8n8.x4.shared.b16 {%0,%1,%2,%3}, [%4];" \
                 : "=r"(r0), "=r"(r1), "=r"(r2), "=r"(r3) : "r"(addr))

__device__ __forceinline__ void mma_s8(int* c, const uint32_t* a, const uint32_t* b) {
    asm volatile(
        "mma.sync.aligned.m16n8k32.row.col.s32.s8.s8.s32 "
        "{%0,%1,%2,%3}, {%4,%5,%6,%7}, {%8,%9}, {%0,%1,%2,%3};\n"
        : "+r"(c[0]), "+r"(c[1]), "+r"(c[2]), "+r"(c[3])
        : "r"(a[0]), "r"(a[1]), "r"(a[2]), "r"(a[3]), "r"(b[0]), "r"(b[1]));
}

// ---------------- init ----------------
__global__ void k_init() {
    if (threadIdx.x == 0) {
        g_stats[0] = 0xFFFFFFFFu; g_stats[1] = 0u;
        g_stats[2] = 0u;          g_stats[3] = 0u;
        g_stats[4] = 0xFFFFFFFFu; g_stats[5] = 0u;
    }
}

// ---------------- global min/max of x ----------------
__global__ void k_minmax_x(const float4* __restrict__ x, int n4) {
    float lmin = 3.4e38f, lmax = -3.4e38f;
    for (int i = blockIdx.x * blockDim.x + threadIdx.x; i < n4; i += gridDim.x * blockDim.x) {
        float4 v = x[i];
        lmin = fminf(lmin, fminf(fminf(v.x, v.y), fminf(v.z, v.w)));
        lmax = fmaxf(lmax, fmaxf(fmaxf(v.x, v.y), fmaxf(v.z, v.w)));
    }
    #pragma unroll
    for (int o = 16; o; o >>= 1) {
        lmin = fminf(lmin, __shfl_xor_sync(0xffffffffu, lmin, o));
        lmax = fmaxf(lmax, __shfl_xor_sync(0xffffffffu, lmax, o));
    }
    __shared__ float sm[2][8];
    if ((threadIdx.x & 31) == 0) { sm[0][threadIdx.x >> 5] = lmin; sm[1][threadIdx.x >> 5] = lmax; }
    __syncthreads();
    if (threadIdx.x == 0) {
        float m = sm[0][0], M = sm[1][0];
        #pragma unroll
        for (int w = 1; w < 8; w++) { m = fminf(m, sm[0][w]); M = fmaxf(M, sm[1][w]); }
        atomicMin(&g_stats[0], fenc(m));
        atomicMax(&g_stats[1], fenc(M));
    }
}

// ---------------- abs-max of a weight tensor ----------------
__global__ void k_absmax(const float4* __restrict__ w, int n4, int slot) {
    float lmax = 0.0f;
    for (int i = blockIdx.x * blockDim.x + threadIdx.x; i < n4; i += gridDim.x * blockDim.x) {
        float4 v = w[i];
        lmax = fmaxf(lmax, fmaxf(fmaxf(fabsf(v.x), fabsf(v.y)), fmaxf(fabsf(v.z), fabsf(v.w))));
    }
    #pragma unroll
    for (int o = 16; o; o >>= 1) lmax = fmaxf(lmax, __shfl_xor_sync(0xffffffffu, lmax, o));
    __shared__ float sm[8];
    if ((threadIdx.x & 31) == 0) sm[threadIdx.x >> 5] = lmax;
    __syncthreads();
    if (threadIdx.x == 0) {
        float M = sm[0];
        #pragma unroll
        for (int w2 = 1; w2 < 8; w2++) M = fmaxf(M, sm[w2]);
        atomicMax(&g_stats[slot], __float_as_uint(M));
    }
}

// ---------------- finalize input/weight scales ----------------
__global__ void k_fin1() {
    if (threadIdx.x != 0) return;
    float an = fdec(g_stats[0]), ax = fdec(g_stats[1]);
    float sx = fmaxf(__fdiv_rn(ax - an, 255.0f), 1e-8f);
    float zxf = rintf(__fdiv_rn(-an, sx)) - 128.0f;
    zxf = fminf(fmaxf(zxf, -128.0f), 127.0f);
    float sw1 = fmaxf(__fdiv_rn(__uint_as_float(g_stats[2]), 127.0f), 1e-8f);
    float sw2 = fmaxf(__fdiv_rn(__uint_as_float(g_stats[3]), 127.0f), 1e-8f);
    g_scale[0] = sx; g_scale[1] = sw1; g_scale[2] = sw2;
    g_scale[3] = sx * sw1;
    g_zp[0] = (int)zxf;
}

// ---------------- finalize h scales (after GEMM1) ----------------
__global__ void k_fin2() {
    if (threadIdx.x != 0) return;
    float hn = fdec(g_stats[4]), hx = fdec(g_stats[5]);
    float sh = fmaxf(__fdiv_rn(hx - hn, 255.0f), 1e-8f);
    float zhf = rintf(__fdiv_rn(-hn, sh)) - 128.0f;
    zhf = fminf(fmaxf(zhf, -128.0f), 127.0f);
    g_scale[4] = sh;
    g_scale[5] = sh * g_scale[2];
    g_zp[1] = (int)zhf;
}

// ---------------- activation quantize (x or h) ----------------
__global__ void k_quant(const float4* __restrict__ xsrc, size_t n4, int which) {
    const float4* src = which ? (const float4*)g_h : xsrc;
    char4* dst = which ? (char4*)g_hq : (char4*)g_xq;
    float s = which ? g_scale[4] : g_scale[0];
    float zp = (float)(which ? g_zp[1] : g_zp[0]);
    for (size_t i = blockIdx.x * (size_t)blockDim.x + threadIdx.x; i < n4;
         i += (size_t)gridDim.x * blockDim.x) {
        float4 v = src[i];
        float q0 = fminf(fmaxf(rintf(__fdiv_rn(v.x, s)) + zp, -128.0f), 127.0f);
        float q1 = fminf(fmaxf(rintf(__fdiv_rn(v.y, s)) + zp, -128.0f), 127.0f);
        float q2 = fminf(fmaxf(rintf(__fdiv_rn(v.z, s)) + zp, -128.0f), 127.0f);
        float q3 = fminf(fmaxf(rintf(__fdiv_rn(v.w, s)) + zp, -128.0f), 127.0f);
        char4 c; c.x = (char)(int)q0; c.y = (char)(int)q1; c.z = (char)(int)q2; c.w = (char)(int)q3;
        dst[i] = c;
    }
}

// ---------------- weight quantize + per-row sums ----------------
__global__ void k_quantw(const float* __restrict__ W, int cols, int which) {
    int8_t* wq = which ? g_w2q : g_w1q;
    int* rs = which ? g_rs2 : g_rs1;
    float sw = which ? g_scale[2] : g_scale[1];
    int row = blockIdx.x;
    const float4* src = (const float4*)(W + (size_t)row * cols);
    char4* dst = (char4*)(wq + (size_t)row * cols);
    int acc = 0;
    for (int c = threadIdx.x; c < (cols >> 2); c += blockDim.x) {
        float4 v = src[c];
        float q0 = fminf(fmaxf(rintf(__fdiv_rn(v.x, sw)), -127.0f), 127.0f);
        float q1 = fminf(fmaxf(rintf(__fdiv_rn(v.y, sw)), -127.0f), 127.0f);
        float q2 = fminf(fmaxf(rintf(__fdiv_rn(v.z, sw)), -127.0f), 127.0f);
        float q3 = fminf(fmaxf(rintf(__fdiv_rn(v.w, sw)), -127.0f), 127.0f);
        int i0 = (int)q0, i1 = (int)q1, i2 = (int)q2, i3 = (int)q3;
        acc += i0 + i1 + i2 + i3;
        char4 cc; cc.x = (char)i0; cc.y = (char)i1; cc.z = (char)i2; cc.w = (char)i3;
        dst[c] = cc;
    }
    #pragma unroll
    for (int o = 16; o; o >>= 1) acc += __shfl_xor_sync(0xffffffffu, acc, o);
    __shared__ int sm[8];
    if ((threadIdx.x & 31) == 0) sm[threadIdx.x >> 5] = acc;
    __syncthreads();
    if (threadIdx.x == 0) {
        int t = 0;
        #pragma unroll
        for (int w = 0; w < 8; w++) t += sm[w];
        rs[row] = t;
    }
}

// ================= int8 GEMM (mma.sync + ldmatrix + 3-stage cp.async) =================
// C[M,N] = A[M,K] . B[N,K]^T ; K-major int8, SW128-swizzled 128B smem rows
// MODE 1: A=g_xq B=g_w1q -> gelu -> g_h + global min/max ; MODE 0: A=g_hq B=g_w2q -> out
static constexpr int SBM = 128;
static constexpr int SBN = 128;
static constexpr int SBK = 128;
static constexpr int NSTAGE = 3;
static constexpr int STAGE_A = SBM * SBK;               // 16 KB
static constexpr int STAGE_SZ = STAGE_A + SBN * SBK;    // 32 KB
static constexpr int SMEM_DYN = 1024 + NSTAGE * STAGE_SZ;  // 99328

template <int MODE>
__global__ __launch_bounds__(256, 2)
void k_gemm(const float* __restrict__ bias, int N, int K, float* __restrict__ outp) {
    extern __shared__ char dsmem[];
    const int tid = threadIdx.x, wid = tid >> 5, lane = tid & 31;
    const int warp_m = wid & 1;    // 2 warps over M (64 rows each)
    const int warp_n = wid >> 1;   // 4 warps over N (32 cols each)
    const int bm = blockIdx.y, bn = blockIdx.x;

    const int8_t* __restrict__ A = MODE ? g_xq : g_hq;
    const int8_t* __restrict__ B = MODE ? g_w1q : g_w2q;
    const int* __restrict__ rs   = MODE ? g_rs1 : g_rs2;
    float* __restrict__ out      = MODE ? g_h : outp;
    const float sc = MODE ? g_scale[3] : g_scale[5];
    const int   z  = MODE ? g_zp[0] : g_zp[1];

    const uint32_t tiles = (smem_u32(dsmem) + 1023) & ~1023u;

    // ---- per-lane ldmatrix offsets (within a stage's A / B tile) ----
    uint32_t offA[4], offB[2];
    {
        int rbase = warp_m * 64 + (lane & 7) + ((lane >> 3) & 1) * 8;
        int cA = ((lane >> 4) & 1) * 16;
        #pragma unroll
        for (int im = 0; im < 4; im++) {
            int row = rbase + im * 16;
            offA[im] = SWZ((uint32_t)(row * 128 + cA));
        }
        int nbase = warp_n * 32 + (lane & 7) + ((lane >> 4) & 1) * 8;
        int cB = ((lane >> 3) & 1) * 16;
        #pragma unroll
        for (int ig = 0; ig < 2; ig++) {
            int row = nbase + ig * 16;
            offB[ig] = SWZ((uint32_t)(row * 128 + cB));
        }
    }

    int c[4][4][4];
    #pragma unroll
    for (int i = 0; i < 4; i++)
        #pragma unroll
        for (int j = 0; j < 4; j++)
            #pragma unroll
            for (int k = 0; k < 4; k++) c[i][j][k] = 0;

    auto load_stage = [&](int s, int kt) {
        uint32_t abase = tiles + s * STAGE_SZ;
        uint32_t bbase = abase + STAGE_A;
        const int8_t* Ag = A + (size_t)(bm * SBM) * K + (size_t)kt * SBK;
        const int8_t* Bg = B + (size_t)(bn * SBN) * K + (size_t)kt * SBK;
        #pragma unroll
        for (int i = 0; i < 4; i++) {
            int idx = tid + i * 256;
            int row = idx >> 3, cc2 = (idx & 7) * 16;
            CP_ASYNC16(abase + SWZ((uint32_t)(row * 128 + cc2)), Ag + (size_t)row * K + cc2);
        }
        #pragma unroll
        for (int i = 0; i < 4; i++) {
            int idx = tid + i * 256;
            int row = idx >> 3, cc2 = (idx & 7) * 16;
            CP_ASYNC16(bbase + SWZ((uint32_t)(row * 128 + cc2)), Bg + (size_t)row * K + cc2);
        }
    };

    const int KT = K >> 7;            // K / 128  (8 or 32)
    load_stage(0, 0); CP_COMMIT();
    load_stage(1, 1); CP_COMMIT();

    for (int kt = 0; kt < KT; kt++) {
        const int s = kt - (kt / NSTAGE) * NSTAGE;   // kt % 3
        CP_WAIT1();
        __syncthreads();

        const uint32_t abase = tiles + s * STAGE_SZ;
        const uint32_t bbase = abase + STAGE_A;
        #pragma unroll
        for (int kk = 0; kk < SBK; kk += 32) {
            uint32_t a[4][4], b[4][2];
            #pragma unroll
            for (int im = 0; im < 4; im++)
                LDSM_X4(a[im][0], a[im][1], a[im][2], a[im][3], (abase + offA[im]) ^ kk);
            #pragma unroll
            for (int ig = 0; ig < 2; ig++)
                LDSM_X4(b[2 * ig][0], b[2 * ig][1], b[2 * ig + 1][0], b[2 * ig + 1][1],
                        (bbase + offB[ig]) ^ kk);
            #pragma unroll
            for (int im = 0; im < 4; im++)
                #pragma unroll
                for (int in = 0; in < 4; in++)
                    mma_s8(c[im][in], a[im], b[in]);
        }

        const int nk = kt + 2;
        if (nk < KT) {
            const int ns = nk - (nk / NSTAGE) * NSTAGE;
            load_stage(ns, nk);
        }
        CP_COMMIT();
    }

    // -------- epilogue --------
    float lmin = 3.4e38f, lmax = -3.4e38f;
    #pragma unroll
    for (int in = 0; in < 4; in++) {
        int col = bn * SBN + warp_n * 32 + in * 8 + (lane & 3) * 2;
        int rs0 = rs[col], rs1v = rs[col + 1];
        float b0 = bias[col], b1v = bias[col + 1];
        #pragma unroll
        for (int im = 0; im < 4; im++) {
            int row = bm * SBM + warp_m * 64 + im * 16 + (lane >> 2);
            float v0 = (float)(c[im][in][0] - z * rs0) * sc + b0;
            float v1 = (float)(c[im][in][1] - z * rs1v) * sc + b1v;
            float v2 = (float)(c[im][in][2] - z * rs0) * sc + b0;
            float v3 = (float)(c[im][in][3] - z * rs1v) * sc + b1v;
            if (MODE) {
                v0 = gelu_exact(v0); v1 = gelu_exact(v1);
                v2 = gelu_exact(v2); v3 = gelu_exact(v3);
                lmin = fminf(lmin, fminf(fminf(v0, v1), fminf(v2, v3)));
                lmax = fmaxf(lmax, fmaxf(fmaxf(v0, v1), fmaxf(v2, v3)));
            }
            *(float2*)(out + (size_t)row * N + col) = make_float2(v0, v1);
            *(float2*)(out + (size_t)(row + 8) * N + col) = make_float2(v2, v3);
        }
    }

    if (MODE) {
        #pragma unroll
        for (int o = 16; o; o >>= 1) {
            lmin = fminf(lmin, __shfl_xor_sync(0xffffffffu, lmin, o));
            lmax = fmaxf(lmax, __shfl_xor_sync(0xffffffffu, lmax, o));
        }
        __shared__ float red[2][8];
        if (lane == 0) { red[0][wid] = lmin; red[1][wid] = lmax; }
        __syncthreads();
        if (tid == 0) {
            float m = red[0][0], Mx = red[1][0];
            #pragma unroll
            for (int w = 1; w < 8; w++) { m = fminf(m, red[0][w]); Mx = fmaxf(Mx, red[1][w]); }
            atomicMin(&g_stats[4], fenc(m));
            atomicMax(&g_stats[5], fenc(Mx));
        }
    }
}

// ---------------- launch ----------------
extern "C" void kernel_launch(void* const* d_in, const int* in_sizes, int n_in,
                              void* d_out, int out_size) {
    const float* x  = (const float*)d_in[0];
    const float* W1 = (const float*)d_in[1];
    const float* b1 = (const float*)d_in[2];
    const float* W2 = (const float*)d_in[3];
    const float* b2 = (const float*)d_in[4];
    float* out = (float*)d_out;

    const size_t nx = (size_t)M_DIM * D_DIM;
    const size_t nh = (size_t)M_DIM * H_DIM;

    cudaFuncSetAttribute(k_gemm<1>, cudaFuncAttributeMaxDynamicSharedMemorySize, SMEM_DYN);
    cudaFuncSetAttribute(k_gemm<0>, cudaFuncAttributeMaxDynamicSharedMemorySize, SMEM_DYN);

    k_init<<<1, 32>>>();
    k_minmax_x<<<2048, 256>>>((const float4*)x, (int)(nx / 4));
    k_absmax<<<512, 256>>>((const float4*)W1, (int)((size_t)H_DIM * D_DIM / 4), 2);
    k_absmax<<<512, 256>>>((const float4*)W2, (int)((size_t)D_DIM * H_DIM / 4), 3);
    k_fin1<<<1, 32>>>();
    k_quant<<<2048, 256>>>((const float4*)x, nx / 4, 0);
    k_quantw<<<H_DIM, 256>>>(W1, D_DIM, 0);
    k_quantw<<<D_DIM, 256>>>(W2, H_DIM, 1);

    // GEMM1: C[16384,4096] = xq[16384,1024] . W1q[4096,1024]^T
    dim3 g1(H_DIM / SBN, M_DIM / SBM);   // (32, 128)
    k_gemm<1><<<g1, 256, SMEM_DYN>>>(b1, H_DIM, D_DIM, nullptr);

    k_fin2<<<1, 32>>>();
    k_quant<<<4096, 256>>>(nullptr, nh / 4, 1);

    // GEMM2: C[16384,1024] = hq[16384,4096] . W2q[1024,4096]^T   (N=D_DIM, K=H_DIM!)
    dim3 g2(D_DIM / SBN, M_DIM / SBM);   // (8, 128)
    k_gemm<0><<<g2, 256, SMEM_DYN>>>(b2, D_DIM, H_DIM, out);
}